// round 1
// baseline (speedup 1.0000x reference)
#include <cuda_runtime.h>
#include <cstdint>

// Scratch: YZ[b][m][t], m in [0,512) = Y = Wq@x + bq, m in [512,1024) = Z = Wo@x (no bias)
// 16 * 1024 * 2048 floats = 128 MB (device global; allowed scratch)
__device__ float g_YZ[16 * 1024 * 2048];

#define D_DIM 512
#define T_DIM 2048
#define B_DIM 16

// ---------------------------------------------------------------------------
// Kernel 1: batched SGEMM  C[b][m][n] = sum_k W2[m][k] * x[b][k][n] (+ bq if m<512)
//   W2 = [Wq; Wo] (1024 x 512), x[b] is (512 x 2048)
// Tiling: 128x128 block tile, BK=16, 8x8 per-thread microtile, 256 threads.
// ---------------------------------------------------------------------------
__global__ void __launch_bounds__(256) gemm_kernel(
    const float* __restrict__ x,
    const float* __restrict__ Wq,
    const float* __restrict__ bq,
    const float* __restrict__ Wo)
{
    __shared__ float As[16][128];   // [k][m] (transposed on load)
    __shared__ float Bs[16][128];   // [k][n]

    const int b  = blockIdx.z;
    const int m0 = blockIdx.y * 128;
    const int n0 = blockIdx.x * 128;

    // whole 128-row block lies entirely in Wq or Wo
    const float* A  = (m0 < D_DIM) ? (Wq + (size_t)m0 * D_DIM)
                                   : (Wo + (size_t)(m0 - D_DIM) * D_DIM);
    const float* Bp = x + (size_t)b * D_DIM * T_DIM;

    const int tid = threadIdx.x;
    const int tx  = tid & 15;    // n direction
    const int ty  = tid >> 4;    // m direction

    float acc[8][8];
    #pragma unroll
    for (int i = 0; i < 8; ++i)
        #pragma unroll
        for (int j = 0; j < 8; ++j) acc[i][j] = 0.0f;

    for (int kt = 0; kt < D_DIM; kt += 16) {
        // Load A tile: 128 rows x 16 k = 512 float4, 2 per thread, store transposed
        #pragma unroll
        for (int it = 0; it < 2; ++it) {
            int idx = tid * 2 + it;          // 0..511
            int row = idx >> 2;              // 0..127
            int kq  = (idx & 3) << 2;        // 0,4,8,12
            float4 v = *(const float4*)(A + (size_t)row * D_DIM + kt + kq);
            As[kq + 0][row] = v.x;
            As[kq + 1][row] = v.y;
            As[kq + 2][row] = v.z;
            As[kq + 3][row] = v.w;
        }
        // Load B tile: 16 k-rows x 128 n = 512 float4, 2 per thread
        #pragma unroll
        for (int it = 0; it < 2; ++it) {
            int idx = tid * 2 + it;
            int row = idx >> 5;              // 0..15
            int nq  = (idx & 31) << 2;       // 0..124
            *(float4*)&Bs[row][nq] =
                *(const float4*)(Bp + (size_t)(kt + row) * T_DIM + n0 + nq);
        }
        __syncthreads();

        #pragma unroll
        for (int k = 0; k < 16; ++k) {
            float ra[8], rb[8];
            *(float4*)&ra[0] = *(const float4*)&As[k][ty * 8];
            *(float4*)&ra[4] = *(const float4*)&As[k][ty * 8 + 4];
            *(float4*)&rb[0] = *(const float4*)&Bs[k][tx * 8];
            *(float4*)&rb[4] = *(const float4*)&Bs[k][tx * 8 + 4];
            #pragma unroll
            for (int i = 0; i < 8; ++i)
                #pragma unroll
                for (int j = 0; j < 8; ++j)
                    acc[i][j] += ra[i] * rb[j];
        }
        __syncthreads();
    }

    // Epilogue: add bias (Y rows only) and store
    const bool hasBias = (m0 < D_DIM);
    #pragma unroll
    for (int i = 0; i < 8; ++i) {
        const int m = m0 + ty * 8 + i;
        const float bias = hasBias ? bq[m] : 0.0f;
        float* dst = g_YZ + ((size_t)b * 1024 + m) * T_DIM + n0 + tx * 8;
        float4 o0, o1;
        o0.x = acc[i][0] + bias; o0.y = acc[i][1] + bias;
        o0.z = acc[i][2] + bias; o0.w = acc[i][3] + bias;
        o1.x = acc[i][4] + bias; o1.y = acc[i][5] + bias;
        o1.z = acc[i][6] + bias; o1.w = acc[i][7] + bias;
        *(float4*)(dst)     = o0;
        *(float4*)(dst + 4) = o1;
    }
}

// ---------------------------------------------------------------------------
// Kernel 2: fused banded attention.
//  Per token t:
//    S[o]  = sum_e Y[e][t] * Y[e][t+o-4]   (gram band, o=0..8)
//    Sb    = sum_e Y[e][t] * bq[e]         (energy of padded/OOB windows)
//    energy[o] = (in-range ? S[o] : Sb) / (sqrt(512)*1.5), softmax -> a[o]
//    out[b][d][t] = bo[d] + sum_o a[o] * Z[d][t+o-4]  (Z OOB -> 0)
//  Block: 128 tokens, 256 threads = 128 lanes x 2 e/d-groups.
// ---------------------------------------------------------------------------
__global__ void __launch_bounds__(256) attn_kernel(
    const float* __restrict__ bq,
    const float* __restrict__ bo,
    float* __restrict__ out)
{
    __shared__ float sRow[16][144];        // 16 rows x (128 + 8 halo), padded
    __shared__ float sPart[2][128][10];    // partial S[0..8], Sb per lane per group
    __shared__ float sbq[D_DIM];
    __shared__ float sbo[D_DIM];

    const int b    = blockIdx.y;
    const int t0   = blockIdx.x * 128;
    const int tid  = threadIdx.x;
    const int lane = tid & 127;            // token within tile
    const int grp  = tid >> 7;             // 0 or 1
    const int tt   = t0 + lane;

    const float* Y = g_YZ + (size_t)b * 1024 * T_DIM;
    const float* Z = Y + (size_t)D_DIM * T_DIM;

    for (int i = tid; i < D_DIM; i += 256) { sbq[i] = bq[i]; sbo[i] = bo[i]; }

    float S[9];
    #pragma unroll
    for (int o = 0; o < 9; ++o) S[o] = 0.0f;
    float Sb = 0.0f;

    // ---- Phase A: gram band over e (split across 2 groups) ----
    for (int e0 = 0; e0 < D_DIM; e0 += 16) {
        for (int i = tid; i < 16 * 136; i += 256) {
            int r = i / 136;
            int c = i - r * 136;
            int t = t0 - 4 + c;
            sRow[r][c] = (t >= 0 && t < T_DIM)
                         ? Y[(size_t)(e0 + r) * T_DIM + t] : 0.0f;
        }
        __syncthreads();
        #pragma unroll
        for (int r = 0; r < 8; ++r) {
            const int rr = grp * 8 + r;
            const float cen = sRow[rr][lane + 4];
            #pragma unroll
            for (int o = 0; o < 9; ++o) S[o] += cen * sRow[rr][lane + o];
            Sb += cen * sbq[e0 + rr];
        }
        __syncthreads();
    }

    #pragma unroll
    for (int o = 0; o < 9; ++o) sPart[grp][lane][o] = S[o];
    sPart[grp][lane][9] = Sb;
    __syncthreads();

    // ---- Softmax (each thread, redundantly per group, for its token) ----
    float a[9];
    const float inv = 1.0f / (22.62741699796952f * 1.5f);  // 1/(sqrt(512)*TEMP)
    const float SbT = sPart[0][lane][9] + sPart[1][lane][9];
    float mx = -1e30f;
    #pragma unroll
    for (int o = 0; o < 9; ++o) {
        float s = sPart[0][lane][o] + sPart[1][lane][o];
        const int ts = tt + o - 4;
        if (ts < 0 || ts >= T_DIM) s = SbT;   // padded window: K = bq
        a[o] = s * inv;
        mx = fmaxf(mx, a[o]);
    }
    float sum = 0.0f;
    #pragma unroll
    for (int o = 0; o < 9; ++o) { a[o] = __expf(a[o] - mx); sum += a[o]; }
    const float rs = 1.0f / sum;
    #pragma unroll
    for (int o = 0; o < 9; ++o) a[o] *= rs;
    __syncthreads();

    // ---- Phase B: weighted banded combine over Z, write (B,D,T) output ----
    for (int d0 = 0; d0 < D_DIM; d0 += 16) {
        for (int i = tid; i < 16 * 136; i += 256) {
            int r = i / 136;
            int c = i - r * 136;
            int t = t0 - 4 + c;
            sRow[r][c] = (t >= 0 && t < T_DIM)
                         ? Z[(size_t)(d0 + r) * T_DIM + t] : 0.0f;
        }
        __syncthreads();
        #pragma unroll
        for (int r = 0; r < 8; ++r) {
            const int rr = grp * 8 + r;
            float acc = sbo[d0 + rr];
            #pragma unroll
            for (int o = 0; o < 9; ++o) acc += a[o] * sRow[rr][lane + o];
            out[((size_t)b * D_DIM + d0 + rr) * T_DIM + tt] = acc;
        }
        __syncthreads();
    }
}

// ---------------------------------------------------------------------------
// Launch
// ---------------------------------------------------------------------------
extern "C" void kernel_launch(void* const* d_in, const int* in_sizes, int n_in,
                              void* d_out, int out_size)
{
    const float* x  = (const float*)d_in[0];
    const float* Wq = (const float*)d_in[1];
    const float* bq = (const float*)d_in[2];
    const float* Wo = (const float*)d_in[3];
    const float* bo = (const float*)d_in[4];
    float* out = (float*)d_out;

    dim3 g1(T_DIM / 128, 1024 / 128, B_DIM);   // (16, 8, 16)
    gemm_kernel<<<g1, 256>>>(x, Wq, bq, Wo);

    dim3 g2(T_DIM / 128, B_DIM);               // (16, 16)
    attn_kernel<<<g2, 256>>>(bq, bo, out);
}

// round 9
// speedup vs baseline: 1.9362x; 1.9362x over previous
#include <cuda_runtime.h>
#include <cuda_bf16.h>
#include <cstdint>

#define D_DIM 512
#define T_DIM 2048
#define B_DIM 16

// ---------------- device scratch ----------------
__device__ __align__(128) float g_YZ[16 * 1024 * 2048];            // Y rows 0..511, Z rows 512..1023
__device__ __align__(128) __nv_bfloat16 g_Ah[1024 * 512];          // [Wq;Wo] hi,  [m][k]
__device__ __align__(128) __nv_bfloat16 g_Al[1024 * 512];          // lo
__device__ __align__(128) __nv_bfloat16 g_Bh[16 * 512 * 2048];     // x hi, [b][k][t]
__device__ __align__(128) __nv_bfloat16 g_Bl[16 * 512 * 2048];     // lo
__device__ __align__(128) float g_Spart[4 * 16 * 2048 * 16];       // partial gram sums (row stride 16)
__device__ __align__(128) float g_attnW[16 * 2048 * 16];           // attention weights (row stride 16)

// ---------------- PTX helpers (compute_100-safe: Ampere-era ops only) ------
__device__ __forceinline__ uint32_t smem_u32(const void* p) {
    uint32_t a;
    asm("{ .reg .u64 t; cvta.to.shared.u64 t, %1; cvt.u32.u64 %0, t; }" : "=r"(a) : "l"(p));
    return a;
}
__device__ __forceinline__ void cpasync16(uint32_t dst, const void* src) {
    asm volatile("cp.async.cg.shared.global [%0], [%1], 16;" :: "r"(dst), "l"(src));
}
#define CP_COMMIT() asm volatile("cp.async.commit_group;" ::: "memory")
#define CP_WAIT1()  asm volatile("cp.async.wait_group 1;" ::: "memory")
#define CP_WAIT0()  asm volatile("cp.async.wait_group 0;" ::: "memory")

__device__ __forceinline__ void ldsm4(uint32_t* r, uint32_t addr) {
    asm volatile("ldmatrix.sync.aligned.m8n8.x4.shared.b16 {%0,%1,%2,%3}, [%4];"
                 : "=r"(r[0]), "=r"(r[1]), "=r"(r[2]), "=r"(r[3]) : "r"(addr));
}
__device__ __forceinline__ void ldsm4t(uint32_t* r, uint32_t addr) {
    asm volatile("ldmatrix.sync.aligned.m8n8.x4.trans.shared.b16 {%0,%1,%2,%3}, [%4];"
                 : "=r"(r[0]), "=r"(r[1]), "=r"(r[2]), "=r"(r[3]) : "r"(addr));
}
__device__ __forceinline__ void mma_bf16(float* d, const uint32_t* a, const uint32_t* b) {
    asm volatile(
        "mma.sync.aligned.m16n8k16.row.col.f32.bf16.bf16.f32 "
        "{%0,%1,%2,%3}, {%4,%5,%6,%7}, {%8,%9}, {%0,%1,%2,%3};"
        : "+f"(d[0]), "+f"(d[1]), "+f"(d[2]), "+f"(d[3])
        : "r"(a[0]), "r"(a[1]), "r"(a[2]), "r"(a[3]), "r"(b[0]), "r"(b[1]));
}

// ---------------------------------------------------------------------------
// Converts (identical to Round-4-passing versions)
// ---------------------------------------------------------------------------
__global__ void __launch_bounds__(256) convert_w_kernel(
    const float* __restrict__ Wq, const float* __restrict__ Wo)
{
    int idx = blockIdx.x * 256 + threadIdx.x;      // 0 .. 1024*512-1
    float v = (idx < D_DIM * D_DIM) ? Wq[idx] : Wo[idx - D_DIM * D_DIM];
    __nv_bfloat16 h = __float2bfloat16(v);
    g_Ah[idx] = h;
    g_Al[idx] = __float2bfloat16(v - __bfloat162float(h));
}

__global__ void __launch_bounds__(256) convert_x_kernel(const float* __restrict__ x)
{
    size_t i4 = ((size_t)blockIdx.x * 256 + threadIdx.x) * 4;
    float4 v = *(const float4*)(x + i4);
    __nv_bfloat16 h0 = __float2bfloat16(v.x), h1 = __float2bfloat16(v.y);
    __nv_bfloat16 h2 = __float2bfloat16(v.z), h3 = __float2bfloat16(v.w);
    __nv_bfloat16 l0 = __float2bfloat16(v.x - __bfloat162float(h0));
    __nv_bfloat16 l1 = __float2bfloat16(v.y - __bfloat162float(h1));
    __nv_bfloat16 l2 = __float2bfloat16(v.z - __bfloat162float(h2));
    __nv_bfloat16 l3 = __float2bfloat16(v.w - __bfloat162float(h3));
    __nv_bfloat162 hh01; hh01.x = h0; hh01.y = h1;
    __nv_bfloat162 hh23; hh23.x = h2; hh23.y = h3;
    __nv_bfloat162 ll01; ll01.x = l0; ll01.y = l1;
    __nv_bfloat162 ll23; ll23.x = l2; ll23.y = l3;
    *(__nv_bfloat162*)(g_Bh + i4)     = hh01;
    *(__nv_bfloat162*)(g_Bh + i4 + 2) = hh23;
    *(__nv_bfloat162*)(g_Bl + i4)     = ll01;
    *(__nv_bfloat162*)(g_Bl + i4 + 2) = ll23;
}

// ---------------------------------------------------------------------------
// HMMA GEMM (identical to Round-4-passing version):
// C[b][m][n] = sum_k W2[m][k] * x[b][k][n] (+bq for m<512)
// split-bf16 3-term. Block 128x128, BK=32, 8 warps (4m x 2n), cp.async 2-stage.
// ---------------------------------------------------------------------------
#define BK 32
#define A_STRIDE 40          // halves per A row  (32 data + 8 pad -> 80B)
#define B_STRIDE 136         // halves per B row  (128 data + 8 pad -> 272B)
#define A_TILE_H (128 * A_STRIDE)              // 5120 halves
#define B_TILE_H (BK * B_STRIDE)               // 4352 halves
#define STAGE_H  (2 * A_TILE_H + 2 * B_TILE_H) // 18944 halves
#define GEMM_SMEM_BYTES (2 * STAGE_H * 2)      // 75776 B

__global__ void __launch_bounds__(256) mma_gemm_kernel(const float* __restrict__ bq)
{
    extern __shared__ __align__(16) __nv_bfloat16 smem[];
    const uint32_t smem_base = smem_u32(smem);
    const int tid  = threadIdx.x;
    const int wid  = tid >> 5;
    const int lane = tid & 31;
    const int b    = blockIdx.z;
    const int m0   = blockIdx.y * 128;
    const int n0   = blockIdx.x * 128;

    const int wm = (wid >> 1) * 32;     // warp m offset in tile
    const int wn = (wid & 1) * 64;      // warp n offset in tile

    // ---- per-thread gmem->smem mapping ----
    const int ar = tid >> 1;            // A row 0..127
    const int au = (tid & 1) * 2;       // A 16B-unit base 0 or 2 (units of 8 halves)
    const int br = tid >> 3;            // B row 0..31
    const int bu = (tid & 7) * 2;       // B 16B-unit base (units of 8 halves)

    const __nv_bfloat16* gAh = g_Ah + (size_t)(m0 + ar) * D_DIM;
    const __nv_bfloat16* gAl = g_Al + (size_t)(m0 + ar) * D_DIM;
    const __nv_bfloat16* gBh = g_Bh + ((size_t)b * D_DIM + br) * T_DIM + n0;
    const __nv_bfloat16* gBl = g_Bl + ((size_t)b * D_DIM + br) * T_DIM + n0;

    // smem stage layout (halves): [Ah | Al | Bh | Bl]
    auto stage_base = [&](int s) -> uint32_t { return smem_base + (uint32_t)s * STAGE_H * 2; };

    auto load_stage = [&](int kt, int s) {
        uint32_t sb = stage_base(s);
        uint32_t aOffH = (uint32_t)(ar * A_STRIDE + au * 8) * 2;   // bytes
        uint32_t bOffH = (uint32_t)(br * B_STRIDE + bu * 8) * 2;
        cpasync16(sb + aOffH,      gAh + kt + au * 8);
        cpasync16(sb + aOffH + 16, gAh + kt + au * 8 + 8);
        cpasync16(sb + A_TILE_H * 2 + aOffH,      gAl + kt + au * 8);
        cpasync16(sb + A_TILE_H * 2 + aOffH + 16, gAl + kt + au * 8 + 8);
        const __nv_bfloat16* ph = gBh + (size_t)kt * T_DIM;
        cpasync16(sb + 2 * A_TILE_H * 2 + bOffH,      ph + bu * 8);
        cpasync16(sb + 2 * A_TILE_H * 2 + bOffH + 16, ph + bu * 8 + 8);
        const __nv_bfloat16* pl = gBl + (size_t)kt * T_DIM;
        cpasync16(sb + (2 * A_TILE_H + B_TILE_H) * 2 + bOffH,      pl + bu * 8);
        cpasync16(sb + (2 * A_TILE_H + B_TILE_H) * 2 + bOffH + 16, pl + bu * 8 + 8);
    };

    float acc[2][8][4];
    #pragma unroll
    for (int i = 0; i < 2; ++i)
        #pragma unroll
        for (int j = 0; j < 8; ++j)
            #pragma unroll
            for (int q = 0; q < 4; ++q) acc[i][j][q] = 0.0f;

    load_stage(0, 0);
    CP_COMMIT();

    const int l15 = lane & 15;
    const int lhi = lane >> 4;          // 0/1

    for (int c = 0; c < D_DIM / BK; ++c) {
        const int s = c & 1;
        if (c + 1 < D_DIM / BK) { load_stage((c + 1) * BK, s ^ 1); CP_COMMIT(); CP_WAIT1(); }
        else                    { CP_WAIT0(); }
        __syncthreads();

        const uint32_t sb  = stage_base(s);
        const uint32_t sAh = sb;
        const uint32_t sAl = sb + A_TILE_H * 2;
        const uint32_t sBh = sb + 2 * A_TILE_H * 2;
        const uint32_t sBl = sb + (2 * A_TILE_H + B_TILE_H) * 2;

        #pragma unroll
        for (int kk = 0; kk < BK; kk += 16) {
            uint32_t ah[2][4], al[2][4];
            const uint32_t aAddr = (uint32_t)(((wm + l15) * A_STRIDE) + kk + lhi * 8) * 2;
            #pragma unroll
            for (int mi = 0; mi < 2; ++mi) {
                ldsm4(ah[mi], sAh + aAddr + (uint32_t)(mi * 16 * A_STRIDE) * 2);
                ldsm4(al[mi], sAl + aAddr + (uint32_t)(mi * 16 * A_STRIDE) * 2);
            }
            const uint32_t bAddr = (uint32_t)(((kk + l15) * B_STRIDE) + wn + lhi * 8) * 2;
            #pragma unroll
            for (int ni = 0; ni < 4; ++ni) {           // 16 n-cols per iter
                uint32_t bh[4], bl[4];
                ldsm4t(bh, sBh + bAddr + (uint32_t)(ni * 16) * 2);
                ldsm4t(bl, sBl + bAddr + (uint32_t)(ni * 16) * 2);
                #pragma unroll
                for (int mi = 0; mi < 2; ++mi) {
                    mma_bf16(acc[mi][ni * 2 + 0], ah[mi], bh + 0);
                    mma_bf16(acc[mi][ni * 2 + 1], ah[mi], bh + 2);
                    mma_bf16(acc[mi][ni * 2 + 0], ah[mi], bl + 0);
                    mma_bf16(acc[mi][ni * 2 + 1], ah[mi], bl + 2);
                    mma_bf16(acc[mi][ni * 2 + 0], al[mi], bh + 0);
                    mma_bf16(acc[mi][ni * 2 + 1], al[mi], bh + 2);
                }
            }
        }
        __syncthreads();
    }

    // ---- epilogue: bias + store to g_YZ ----
    const bool hasBias = (m0 < D_DIM);
    const int row = lane >> 2;
    const int col = (lane & 3) * 2;
    #pragma unroll
    for (int mi = 0; mi < 2; ++mi) {
        const int mA = m0 + wm + mi * 16 + row;
        const float biasA = hasBias ? bq[mA] : 0.0f;
        const float biasB = hasBias ? bq[mA + 8] : 0.0f;
        float* dA = g_YZ + ((size_t)b * 1024 + mA) * T_DIM + n0 + wn + col;
        float* dB = dA + (size_t)8 * T_DIM;
        #pragma unroll
        for (int ni = 0; ni < 8; ++ni) {
            float2 v0, v1;
            v0.x = acc[mi][ni][0] + biasA; v0.y = acc[mi][ni][1] + biasA;
            v1.x = acc[mi][ni][2] + biasB; v1.y = acc[mi][ni][3] + biasB;
            *(float2*)(dA + ni * 8) = v0;
            *(float2*)(dB + ni * 8) = v1;
        }
    }
}

// ---------------------------------------------------------------------------
// Gram partial: S[o][t] += sum_{e in chunk} Y[e][t]*Y[e][t+o-4]; Sb += Y[e][t]*bq[e]
// grid (16 t-tiles, 16 b, 4 e-chunks), 512 threads = 128 token-lanes x 4 groups
// ---------------------------------------------------------------------------
#define GRAM_SMEM ((128 * 144 + 4 * 128 * 10 + 128) * 4)

__global__ void __launch_bounds__(512) gram_kernel(const float* __restrict__ bq)
{
    extern __shared__ float sm[];
    float* tile = sm;                       // [128][144]
    float* sP   = sm + 128 * 144;           // [4][128][10]
    float* sbq  = sP + 4 * 128 * 10;        // [128]

    const int tid  = threadIdx.x;
    const int lane = tid & 127;
    const int grp  = tid >> 7;
    const int t0   = blockIdx.x * 128;
    const int b    = blockIdx.y;
    const int e0   = blockIdx.z * 128;

    if (tid < 128) sbq[tid] = bq[e0 + tid];

    const float* Ybase = g_YZ + ((size_t)b * 1024 + e0) * T_DIM;
    // load 128 rows x 144 cols (t = t0-8 .. t0+135), zero-padded, float4
    for (int i = tid; i < 128 * 36; i += 512) {
        const int r = i / 36;
        const int j = i - r * 36;
        const int t = t0 - 8 + j * 4;
        const float* rp = Ybase + (size_t)r * T_DIM;
        float4 v;
        if ((unsigned)t <= 2044u) {
            v = *(const float4*)(rp + t);
        } else {
            v.x = ((unsigned)(t + 0) < 2048u) ? rp[t + 0] : 0.0f;
            v.y = ((unsigned)(t + 1) < 2048u) ? rp[t + 1] : 0.0f;
            v.z = ((unsigned)(t + 2) < 2048u) ? rp[t + 2] : 0.0f;
            v.w = ((unsigned)(t + 3) < 2048u) ? rp[t + 3] : 0.0f;
        }
        *(float4*)&tile[r * 144 + j * 4] = v;
    }
    __syncthreads();

    float S[10];
    #pragma unroll
    for (int o = 0; o < 10; ++o) S[o] = 0.0f;

    for (int q = 0; q < 32; ++q) {
        const int rr = grp * 32 + q;
        const float* trow = &tile[rr * 144];
        const float cen = trow[lane + 8];
        #pragma unroll
        for (int o = 0; o < 9; ++o) S[o] += cen * trow[lane + 4 + o];
        S[9] += cen * sbq[rr];
    }

    #pragma unroll
    for (int o = 0; o < 10; ++o) sP[(grp * 128 + lane) * 10 + o] = S[o];
    __syncthreads();

    if (grp == 0) {
        float* dst = g_Spart + ((size_t)(blockIdx.z * 16 + b) * T_DIM + t0 + lane) * 16;
        #pragma unroll
        for (int o = 0; o < 10; ++o) {
            dst[o] = sP[(0 * 128 + lane) * 10 + o] + sP[(1 * 128 + lane) * 10 + o]
                   + sP[(2 * 128 + lane) * 10 + o] + sP[(3 * 128 + lane) * 10 + o];
        }
    }
}

// ---------------------------------------------------------------------------
// Softmax: reduce partials, OOB windows -> Sb, write normalized weights
// ---------------------------------------------------------------------------
__global__ void __launch_bounds__(256) softmax_kernel()
{
    const int idx = blockIdx.x * 256 + threadIdx.x;      // 0 .. 16*2048-1
    const int t = idx & 2047;

    float S[10];
    #pragma unroll
    for (int o = 0; o < 10; ++o) S[o] = 0.0f;
    #pragma unroll
    for (int c = 0; c < 4; ++c) {
        const float* p = g_Spart + ((size_t)c * 16 * T_DIM + idx) * 16;
        #pragma unroll
        for (int o = 0; o < 10; ++o) S[o] += p[o];
    }

    const float inv = 1.0f / (22.62741699796952f * 1.5f);   // 1/(sqrt(512)*TEMP)
    float a[9];
    float mx = -1e30f;
    #pragma unroll
    for (int o = 0; o < 9; ++o) {
        float s = S[o];
        const int ts = t + o - 4;
        if (ts < 0 || ts >= T_DIM) s = S[9];
        a[o] = s * inv;
        mx = fmaxf(mx, a[o]);
    }
    float sum = 0.0f;
    #pragma unroll
    for (int o = 0; o < 9; ++o) { a[o] = __expf(a[o] - mx); sum += a[o]; }
    const float rs = 1.0f / sum;
    float* dst = g_attnW + (size_t)idx * 16;
    #pragma unroll
    for (int o = 0; o < 9; ++o) dst[o] = a[o] * rs;
}

// ---------------------------------------------------------------------------
// Combine: out[b][d][t] = bo[d] + sum_o a[t][o] * Z[d][t+o-4]
// grid (16 t-tiles, 16 b, 4 d-chunks), 512 threads = 128 lanes x 4 groups
// ---------------------------------------------------------------------------
#define COMB_SMEM ((128 * 144 + 128) * 4)

__global__ void __launch_bounds__(512) combine_kernel(
    const float* __restrict__ bo, float* __restrict__ out)
{
    extern __shared__ float sm[];
    float* tile = sm;                   // [128][144]
    float* sbo  = sm + 128 * 144;       // [128]

    const int tid  = threadIdx.x;
    const int lane = tid & 127;
    const int grp  = tid >> 7;
    const int t0   = blockIdx.x * 128;
    const int b    = blockIdx.y;
    const int d0   = blockIdx.z * 128;

    if (tid < 128) sbo[tid] = bo[d0 + tid];

    const float* Zbase = g_YZ + ((size_t)b * 1024 + D_DIM + d0) * T_DIM;
    for (int i = tid; i < 128 * 36; i += 512) {
        const int r = i / 36;
        const int j = i - r * 36;
        const int t = t0 - 8 + j * 4;
        const float* rp = Zbase + (size_t)r * T_DIM;
        float4 v;
        if ((unsigned)t <= 2044u) {
            v = *(const float4*)(rp + t);
        } else {
            v.x = ((unsigned)(t + 0) < 2048u) ? rp[t + 0] : 0.0f;
            v.y = ((unsigned)(t + 1) < 2048u) ? rp[t + 1] : 0.0f;
            v.z = ((unsigned)(t + 2) < 2048u) ? rp[t + 2] : 0.0f;
            v.w = ((unsigned)(t + 3) < 2048u) ? rp[t + 3] : 0.0f;
        }
        *(float4*)&tile[r * 144 + j * 4] = v;
    }

    float a[9];
    {
        const float* ap = g_attnW + ((size_t)b * T_DIM + t0 + lane) * 16;
        #pragma unroll
        for (int o = 0; o < 9; ++o) a[o] = ap[o];
    }
    __syncthreads();

    float* obase = out + ((size_t)b * D_DIM + d0) * T_DIM + t0 + lane;
    for (int q = 0; q < 32; ++q) {
        const int rr = grp * 32 + q;
        const float* trow = &tile[rr * 144];
        float acc = sbo[rr];
        #pragma unroll
        for (int o = 0; o < 9; ++o) acc += a[o] * trow[lane + 4 + o];
        obase[(size_t)rr * T_DIM] = acc;
    }
}

// ---------------------------------------------------------------------------
// Launch
// ---------------------------------------------------------------------------
extern "C" void kernel_launch(void* const* d_in, const int* in_sizes, int n_in,
                              void* d_out, int out_size)
{
    const float* x  = (const float*)d_in[0];
    const float* Wq = (const float*)d_in[1];
    const float* bq = (const float*)d_in[2];
    const float* Wo = (const float*)d_in[3];
    const float* bo = (const float*)d_in[4];
    float* out = (float*)d_out;

    cudaFuncSetAttribute(mma_gemm_kernel,
                         cudaFuncAttributeMaxDynamicSharedMemorySize, GEMM_SMEM_BYTES);
    cudaFuncSetAttribute(gram_kernel,
                         cudaFuncAttributeMaxDynamicSharedMemorySize, GRAM_SMEM);
    cudaFuncSetAttribute(combine_kernel,
                         cudaFuncAttributeMaxDynamicSharedMemorySize, COMB_SMEM);

    convert_w_kernel<<<(1024 * 512) / 256, 256>>>(Wq, Wo);

    // 16*512*2048 / (256*4) = 16384 blocks
    convert_x_kernel<<<16384, 256>>>(x);

    dim3 gg(T_DIM / 128, 1024 / 128, B_DIM);   // (16, 8, 16)
    mma_gemm_kernel<<<gg, 256, GEMM_SMEM_BYTES>>>(bq);

    dim3 gr(T_DIM / 128, B_DIM, 4);            // (16, 16, 4)
    gram_kernel<<<gr, 512, GRAM_SMEM>>>(bq);

    softmax_kernel<<<(B_DIM * T_DIM) / 256, 256>>>();

    combine_kernel<<<gr, 512, COMB_SMEM>>>(bo, out);
}

// round 10
// speedup vs baseline: 1.9524x; 1.0083x over previous
#include <cuda_runtime.h>
#include <cuda_bf16.h>
#include <cstdint>

#define D_DIM 512
#define T_DIM 2048
#define B_DIM 16
#define BT    (B_DIM * T_DIM)     // 32768 tokens total

// ---------------- device scratch ----------------
__device__ __align__(128) float g_YZ[16 * 1024 * 2048];            // Y rows 0..511, Z rows 512..1023
__device__ __align__(128) __nv_bfloat16 g_Ah[1024 * 512];          // [Wq;Wo] hi,  [m][k]
__device__ __align__(128) __nv_bfloat16 g_Al[1024 * 512];          // lo
__device__ __align__(128) __nv_bfloat16 g_Bh[16 * 512 * 2048];     // x hi, [b][k][t]
__device__ __align__(128) __nv_bfloat16 g_Bl[16 * 512 * 2048];     // lo
__device__ __align__(128) float g_Spart[4 * 10 * BT];              // plane-major: [chunk][o][token]
__device__ __align__(128) float g_attnW[9 * BT];                   // plane-major: [o][token]

// ---------------- PTX helpers (compute_100-safe: Ampere-era ops only) ------
__device__ __forceinline__ uint32_t smem_u32(const void* p) {
    uint32_t a;
    asm("{ .reg .u64 t; cvta.to.shared.u64 t, %1; cvt.u32.u64 %0, t; }" : "=r"(a) : "l"(p));
    return a;
}
__device__ __forceinline__ void cpasync16(uint32_t dst, const void* src) {
    asm volatile("cp.async.cg.shared.global [%0], [%1], 16;" :: "r"(dst), "l"(src));
}
#define CP_COMMIT() asm volatile("cp.async.commit_group;" ::: "memory")
#define CP_WAIT1()  asm volatile("cp.async.wait_group 1;" ::: "memory")
#define CP_WAIT0()  asm volatile("cp.async.wait_group 0;" ::: "memory")

__device__ __forceinline__ void ldsm4(uint32_t* r, uint32_t addr) {
    asm volatile("ldmatrix.sync.aligned.m8n8.x4.shared.b16 {%0,%1,%2,%3}, [%4];"
                 : "=r"(r[0]), "=r"(r[1]), "=r"(r[2]), "=r"(r[3]) : "r"(addr));
}
__device__ __forceinline__ void ldsm4t(uint32_t* r, uint32_t addr) {
    asm volatile("ldmatrix.sync.aligned.m8n8.x4.trans.shared.b16 {%0,%1,%2,%3}, [%4];"
                 : "=r"(r[0]), "=r"(r[1]), "=r"(r[2]), "=r"(r[3]) : "r"(addr));
}
__device__ __forceinline__ void mma_bf16(float* d, const uint32_t* a, const uint32_t* b) {
    asm volatile(
        "mma.sync.aligned.m16n8k16.row.col.f32.bf16.bf16.f32 "
        "{%0,%1,%2,%3}, {%4,%5,%6,%7}, {%8,%9}, {%0,%1,%2,%3};"
        : "+f"(d[0]), "+f"(d[1]), "+f"(d[2]), "+f"(d[3])
        : "r"(a[0]), "r"(a[1]), "r"(a[2]), "r"(a[3]), "r"(b[0]), "r"(b[1]));
}

// ---------------------------------------------------------------------------
// Converts (identical to Round-4/9-passing versions)
// ---------------------------------------------------------------------------
__global__ void __launch_bounds__(256) convert_w_kernel(
    const float* __restrict__ Wq, const float* __restrict__ Wo)
{
    int idx = blockIdx.x * 256 + threadIdx.x;      // 0 .. 1024*512-1
    float v = (idx < D_DIM * D_DIM) ? Wq[idx] : Wo[idx - D_DIM * D_DIM];
    __nv_bfloat16 h = __float2bfloat16(v);
    g_Ah[idx] = h;
    g_Al[idx] = __float2bfloat16(v - __bfloat162float(h));
}

__global__ void __launch_bounds__(256) convert_x_kernel(const float* __restrict__ x)
{
    size_t i4 = ((size_t)blockIdx.x * 256 + threadIdx.x) * 4;
    float4 v = *(const float4*)(x + i4);
    __nv_bfloat16 h0 = __float2bfloat16(v.x), h1 = __float2bfloat16(v.y);
    __nv_bfloat16 h2 = __float2bfloat16(v.z), h3 = __float2bfloat16(v.w);
    __nv_bfloat16 l0 = __float2bfloat16(v.x - __bfloat162float(h0));
    __nv_bfloat16 l1 = __float2bfloat16(v.y - __bfloat162float(h1));
    __nv_bfloat16 l2 = __float2bfloat16(v.z - __bfloat162float(h2));
    __nv_bfloat16 l3 = __float2bfloat16(v.w - __bfloat162float(h3));
    __nv_bfloat162 hh01; hh01.x = h0; hh01.y = h1;
    __nv_bfloat162 hh23; hh23.x = h2; hh23.y = h3;
    __nv_bfloat162 ll01; ll01.x = l0; ll01.y = l1;
    __nv_bfloat162 ll23; ll23.x = l2; ll23.y = l3;
    *(__nv_bfloat162*)(g_Bh + i4)     = hh01;
    *(__nv_bfloat162*)(g_Bh + i4 + 2) = hh23;
    *(__nv_bfloat162*)(g_Bl + i4)     = ll01;
    *(__nv_bfloat162*)(g_Bl + i4 + 2) = ll23;
}

// ---------------------------------------------------------------------------
// HMMA GEMM (identical to twice-passing version):
// C[b][m][n] = sum_k W2[m][k] * x[b][k][n] (+bq for m<512)
// split-bf16 3-term. Block 128x128, BK=32, 8 warps (4m x 2n), cp.async 2-stage.
// ---------------------------------------------------------------------------
#define BK 32
#define A_STRIDE 40          // halves per A row  (32 data + 8 pad -> 80B)
#define B_STRIDE 136         // halves per B row  (128 data + 8 pad -> 272B)
#define A_TILE_H (128 * A_STRIDE)              // 5120 halves
#define B_TILE_H (BK * B_STRIDE)               // 4352 halves
#define STAGE_H  (2 * A_TILE_H + 2 * B_TILE_H) // 18944 halves
#define GEMM_SMEM_BYTES (2 * STAGE_H * 2)      // 75776 B

__global__ void __launch_bounds__(256) mma_gemm_kernel(const float* __restrict__ bq)
{
    extern __shared__ __align__(16) __nv_bfloat16 smem[];
    const uint32_t smem_base = smem_u32(smem);
    const int tid  = threadIdx.x;
    const int wid  = tid >> 5;
    const int lane = tid & 31;
    const int b    = blockIdx.z;
    const int m0   = blockIdx.y * 128;
    const int n0   = blockIdx.x * 128;

    const int wm = (wid >> 1) * 32;     // warp m offset in tile
    const int wn = (wid & 1) * 64;      // warp n offset in tile

    // ---- per-thread gmem->smem mapping ----
    const int ar = tid >> 1;            // A row 0..127
    const int au = (tid & 1) * 2;       // A 16B-unit base 0 or 2 (units of 8 halves)
    const int br = tid >> 3;            // B row 0..31
    const int bu = (tid & 7) * 2;       // B 16B-unit base (units of 8 halves)

    const __nv_bfloat16* gAh = g_Ah + (size_t)(m0 + ar) * D_DIM;
    const __nv_bfloat16* gAl = g_Al + (size_t)(m0 + ar) * D_DIM;
    const __nv_bfloat16* gBh = g_Bh + ((size_t)b * D_DIM + br) * T_DIM + n0;
    const __nv_bfloat16* gBl = g_Bl + ((size_t)b * D_DIM + br) * T_DIM + n0;

    // smem stage layout (halves): [Ah | Al | Bh | Bl]
    auto stage_base = [&](int s) -> uint32_t { return smem_base + (uint32_t)s * STAGE_H * 2; };

    auto load_stage = [&](int kt, int s) {
        uint32_t sb = stage_base(s);
        uint32_t aOffH = (uint32_t)(ar * A_STRIDE + au * 8) * 2;   // bytes
        uint32_t bOffH = (uint32_t)(br * B_STRIDE + bu * 8) * 2;
        cpasync16(sb + aOffH,      gAh + kt + au * 8);
        cpasync16(sb + aOffH + 16, gAh + kt + au * 8 + 8);
        cpasync16(sb + A_TILE_H * 2 + aOffH,      gAl + kt + au * 8);
        cpasync16(sb + A_TILE_H * 2 + aOffH + 16, gAl + kt + au * 8 + 8);
        const __nv_bfloat16* ph = gBh + (size_t)kt * T_DIM;
        cpasync16(sb + 2 * A_TILE_H * 2 + bOffH,      ph + bu * 8);
        cpasync16(sb + 2 * A_TILE_H * 2 + bOffH + 16, ph + bu * 8 + 8);
        const __nv_bfloat16* pl = gBl + (size_t)kt * T_DIM;
        cpasync16(sb + (2 * A_TILE_H + B_TILE_H) * 2 + bOffH,      pl + bu * 8);
        cpasync16(sb + (2 * A_TILE_H + B_TILE_H) * 2 + bOffH + 16, pl + bu * 8 + 8);
    };

    float acc[2][8][4];
    #pragma unroll
    for (int i = 0; i < 2; ++i)
        #pragma unroll
        for (int j = 0; j < 8; ++j)
            #pragma unroll
            for (int q = 0; q < 4; ++q) acc[i][j][q] = 0.0f;

    load_stage(0, 0);
    CP_COMMIT();

    const int l15 = lane & 15;
    const int lhi = lane >> 4;          // 0/1

    for (int c = 0; c < D_DIM / BK; ++c) {
        const int s = c & 1;
        if (c + 1 < D_DIM / BK) { load_stage((c + 1) * BK, s ^ 1); CP_COMMIT(); CP_WAIT1(); }
        else                    { CP_WAIT0(); }
        __syncthreads();

        const uint32_t sb  = stage_base(s);
        const uint32_t sAh = sb;
        const uint32_t sAl = sb + A_TILE_H * 2;
        const uint32_t sBh = sb + 2 * A_TILE_H * 2;
        const uint32_t sBl = sb + (2 * A_TILE_H + B_TILE_H) * 2;

        #pragma unroll
        for (int kk = 0; kk < BK; kk += 16) {
            uint32_t ah[2][4], al[2][4];
            const uint32_t aAddr = (uint32_t)(((wm + l15) * A_STRIDE) + kk + lhi * 8) * 2;
            #pragma unroll
            for (int mi = 0; mi < 2; ++mi) {
                ldsm4(ah[mi], sAh + aAddr + (uint32_t)(mi * 16 * A_STRIDE) * 2);
                ldsm4(al[mi], sAl + aAddr + (uint32_t)(mi * 16 * A_STRIDE) * 2);
            }
            const uint32_t bAddr = (uint32_t)(((kk + l15) * B_STRIDE) + wn + lhi * 8) * 2;
            #pragma unroll
            for (int ni = 0; ni < 4; ++ni) {           // 16 n-cols per iter
                uint32_t bh[4], bl[4];
                ldsm4t(bh, sBh + bAddr + (uint32_t)(ni * 16) * 2);
                ldsm4t(bl, sBl + bAddr + (uint32_t)(ni * 16) * 2);
                #pragma unroll
                for (int mi = 0; mi < 2; ++mi) {
                    mma_bf16(acc[mi][ni * 2 + 0], ah[mi], bh + 0);
                    mma_bf16(acc[mi][ni * 2 + 1], ah[mi], bh + 2);
                    mma_bf16(acc[mi][ni * 2 + 0], ah[mi], bl + 0);
                    mma_bf16(acc[mi][ni * 2 + 1], ah[mi], bl + 2);
                    mma_bf16(acc[mi][ni * 2 + 0], al[mi], bh + 0);
                    mma_bf16(acc[mi][ni * 2 + 1], al[mi], bh + 2);
                }
            }
        }
        __syncthreads();
    }

    // ---- epilogue: bias + store to g_YZ ----
    const bool hasBias = (m0 < D_DIM);
    const int row = lane >> 2;
    const int col = (lane & 3) * 2;
    #pragma unroll
    for (int mi = 0; mi < 2; ++mi) {
        const int mA = m0 + wm + mi * 16 + row;
        const float biasA = hasBias ? bq[mA] : 0.0f;
        const float biasB = hasBias ? bq[mA + 8] : 0.0f;
        float* dA = g_YZ + ((size_t)b * 1024 + mA) * T_DIM + n0 + wn + col;
        float* dB = dA + (size_t)8 * T_DIM;
        #pragma unroll
        for (int ni = 0; ni < 8; ++ni) {
            float2 v0, v1;
            v0.x = acc[mi][ni][0] + biasA; v0.y = acc[mi][ni][1] + biasA;
            v1.x = acc[mi][ni][2] + biasB; v1.y = acc[mi][ni][3] + biasB;
            *(float2*)(dA + ni * 8) = v0;
            *(float2*)(dB + ni * 8) = v1;
        }
    }
}

// ---------------------------------------------------------------------------
// Gram partial: S[o][t] += sum_{e in chunk} Y[e][t]*Y[e][t+o-4]; Sb += Y[e][t]*bq[e]
// grid (16 t-tiles, 16 b, 4 e-chunks), 512 threads = 128 token-lanes x 4 groups
// Output plane-major: g_Spart[(z*10+o)*BT + b*T + t]  (coalesced per o)
// ---------------------------------------------------------------------------
#define GRAM_SMEM ((128 * 144 + 4 * 128 * 10 + 128) * 4)

__global__ void __launch_bounds__(512) gram_kernel(const float* __restrict__ bq)
{
    extern __shared__ float sm[];
    float* tile = sm;                       // [128][144]
    float* sP   = sm + 128 * 144;           // [4][128][10]
    float* sbq  = sP + 4 * 128 * 10;        // [128]

    const int tid  = threadIdx.x;
    const int lane = tid & 127;
    const int grp  = tid >> 7;
    const int t0   = blockIdx.x * 128;
    const int b    = blockIdx.y;
    const int e0   = blockIdx.z * 128;

    if (tid < 128) sbq[tid] = bq[e0 + tid];

    const float* Ybase = g_YZ + ((size_t)b * 1024 + e0) * T_DIM;
    // load 128 rows x 144 cols (t = t0-8 .. t0+135), zero-padded, float4
    for (int i = tid; i < 128 * 36; i += 512) {
        const int r = i / 36;
        const int j = i - r * 36;
        const int t = t0 - 8 + j * 4;
        const float* rp = Ybase + (size_t)r * T_DIM;
        float4 v;
        if ((unsigned)t <= 2044u) {
            v = *(const float4*)(rp + t);
        } else {
            v.x = ((unsigned)(t + 0) < 2048u) ? rp[t + 0] : 0.0f;
            v.y = ((unsigned)(t + 1) < 2048u) ? rp[t + 1] : 0.0f;
            v.z = ((unsigned)(t + 2) < 2048u) ? rp[t + 2] : 0.0f;
            v.w = ((unsigned)(t + 3) < 2048u) ? rp[t + 3] : 0.0f;
        }
        *(float4*)&tile[r * 144 + j * 4] = v;
    }
    __syncthreads();

    float S[10];
    #pragma unroll
    for (int o = 0; o < 10; ++o) S[o] = 0.0f;

    for (int q = 0; q < 32; ++q) {
        const int rr = grp * 32 + q;
        const float* trow = &tile[rr * 144];
        const float cen = trow[lane + 8];
        #pragma unroll
        for (int o = 0; o < 9; ++o) S[o] += cen * trow[lane + 4 + o];
        S[9] += cen * sbq[rr];
    }

    #pragma unroll
    for (int o = 0; o < 10; ++o) sP[(grp * 128 + lane) * 10 + o] = S[o];
    __syncthreads();

    // reduce 4 groups, write plane-major (coalesced: lanes -> consecutive tokens)
    if (grp == 0) {
        const size_t tok = (size_t)b * T_DIM + t0 + lane;
        #pragma unroll
        for (int o = 0; o < 10; ++o) {
            float v = sP[(0 * 128 + lane) * 10 + o] + sP[(1 * 128 + lane) * 10 + o]
                    + sP[(2 * 128 + lane) * 10 + o] + sP[(3 * 128 + lane) * 10 + o];
            g_Spart[((size_t)blockIdx.z * 10 + o) * BT + tok] = v;
        }
    }
}

// ---------------------------------------------------------------------------
// Softmax: reduce partials (plane-major, coalesced), OOB windows -> Sb,
// write normalized weights plane-major (coalesced).
// ---------------------------------------------------------------------------
__global__ void __launch_bounds__(256) softmax_kernel()
{
    const int idx = blockIdx.x * 256 + threadIdx.x;      // 0 .. BT-1
    const int t = idx & 2047;

    float S[10];
    #pragma unroll
    for (int o = 0; o < 10; ++o) {
        S[o] = g_Spart[(size_t)(0 * 10 + o) * BT + idx]
             + g_Spart[(size_t)(1 * 10 + o) * BT + idx]
             + g_Spart[(size_t)(2 * 10 + o) * BT + idx]
             + g_Spart[(size_t)(3 * 10 + o) * BT + idx];
    }

    const float inv = 1.0f / (22.62741699796952f * 1.5f);   // 1/(sqrt(512)*TEMP)
    float a[9];
    float mx = -1e30f;
    #pragma unroll
    for (int o = 0; o < 9; ++o) {
        float s = S[o];
        const int ts = t + o - 4;
        if (ts < 0 || ts >= T_DIM) s = S[9];
        a[o] = s * inv;
        mx = fmaxf(mx, a[o]);
    }
    float sum = 0.0f;
    #pragma unroll
    for (int o = 0; o < 9; ++o) { a[o] = __expf(a[o] - mx); sum += a[o]; }
    const float rs = 1.0f / sum;
    #pragma unroll
    for (int o = 0; o < 9; ++o) g_attnW[(size_t)o * BT + idx] = a[o] * rs;
}

// ---------------------------------------------------------------------------
// Combine: out[b][d][t] = bo[d] + sum_o a[t][o] * Z[d][t+o-4]
// grid (16 t-tiles, 16 b, 4 d-chunks), 512 threads = 128 lanes x 4 groups
// Weights read plane-major (coalesced).
// ---------------------------------------------------------------------------
#define COMB_SMEM ((128 * 144 + 128) * 4)

__global__ void __launch_bounds__(512) combine_kernel(
    const float* __restrict__ bo, float* __restrict__ out)
{
    extern __shared__ float sm[];
    float* tile = sm;                   // [128][144]
    float* sbo  = sm + 128 * 144;       // [128]

    const int tid  = threadIdx.x;
    const int lane = tid & 127;
    const int grp  = tid >> 7;
    const int t0   = blockIdx.x * 128;
    const int b    = blockIdx.y;
    const int d0   = blockIdx.z * 128;

    if (tid < 128) sbo[tid] = bo[d0 + tid];

    const float* Zbase = g_YZ + ((size_t)b * 1024 + D_DIM + d0) * T_DIM;
    for (int i = tid; i < 128 * 36; i += 512) {
        const int r = i / 36;
        const int j = i - r * 36;
        const int t = t0 - 8 + j * 4;
        const float* rp = Zbase + (size_t)r * T_DIM;
        float4 v;
        if ((unsigned)t <= 2044u) {
            v = *(const float4*)(rp + t);
        } else {
            v.x = ((unsigned)(t + 0) < 2048u) ? rp[t + 0] : 0.0f;
            v.y = ((unsigned)(t + 1) < 2048u) ? rp[t + 1] : 0.0f;
            v.z = ((unsigned)(t + 2) < 2048u) ? rp[t + 2] : 0.0f;
            v.w = ((unsigned)(t + 3) < 2048u) ? rp[t + 3] : 0.0f;
        }
        *(float4*)&tile[r * 144 + j * 4] = v;
    }

    float a[9];
    {
        const size_t tok = (size_t)b * T_DIM + t0 + lane;
        #pragma unroll
        for (int o = 0; o < 9; ++o) a[o] = g_attnW[(size_t)o * BT + tok];
    }
    __syncthreads();

    float* obase = out + ((size_t)b * D_DIM + d0) * T_DIM + t0 + lane;
    for (int q = 0; q < 32; ++q) {
        const int rr = grp * 32 + q;
        const float* trow = &tile[rr * 144];
        float acc = sbo[rr];
        #pragma unroll
        for (int o = 0; o < 9; ++o) acc += a[o] * trow[lane + 4 + o];
        obase[(size_t)rr * T_DIM] = acc;
    }
}

// ---------------------------------------------------------------------------
// Launch
// ---------------------------------------------------------------------------
extern "C" void kernel_launch(void* const* d_in, const int* in_sizes, int n_in,
                              void* d_out, int out_size)
{
    const float* x  = (const float*)d_in[0];
    const float* Wq = (const float*)d_in[1];
    const float* bq = (const float*)d_in[2];
    const float* Wo = (const float*)d_in[3];
    const float* bo = (const float*)d_in[4];
    float* out = (float*)d_out;

    cudaFuncSetAttribute(mma_gemm_kernel,
                         cudaFuncAttributeMaxDynamicSharedMemorySize, GEMM_SMEM_BYTES);
    cudaFuncSetAttribute(gram_kernel,
                         cudaFuncAttributeMaxDynamicSharedMemorySize, GRAM_SMEM);
    cudaFuncSetAttribute(combine_kernel,
                         cudaFuncAttributeMaxDynamicSharedMemorySize, COMB_SMEM);

    convert_w_kernel<<<(1024 * 512) / 256, 256>>>(Wq, Wo);

    // 16*512*2048 / (256*4) = 16384 blocks
    convert_x_kernel<<<16384, 256>>>(x);

    dim3 gg(T_DIM / 128, 1024 / 128, B_DIM);   // (16, 8, 16)
    mma_gemm_kernel<<<gg, 256, GEMM_SMEM_BYTES>>>(bq);

    dim3 gr(T_DIM / 128, B_DIM, 4);            // (16, 16, 4)
    gram_kernel<<<gr, 512, GRAM_SMEM>>>(bq);

    softmax_kernel<<<BT / 256, 256>>>();

    combine_kernel<<<gr, 512, COMB_SMEM>>>(bo, out);
}